// round 11
// baseline (speedup 1.0000x reference)
#include <cuda_runtime.h>
#include <mma.h>
#include <math.h>
#include <cstdint>

using namespace nvcuda;

#define BATCH 128
#define NTQ   512
#define NCK   512
#define EMB   256
#define NTOK  (BATCH*NCK)

// ---- device scratch (allocation-free) ----
__device__ float g_K[NTOK*64];      // K padded to 64 dims (60..63 = 0)
__device__ float g_V[NTOK*64];      // V padded to 64 dims
__device__ float g_ikn[NTOK];       // inverse key norms
__device__ float g_Wq[64*256];      // At_w zero-padded to 64 rows
__device__ float g_Wc[128*256];     // [Ac_w; pad4; Bc_w; pad4]
__device__ float g_Rp[256*64];      // R_w padded: [e][dv<60 ? Rw : 0]
__device__ float g_bq[64];
__device__ float g_bc[128];

template<typename F> __device__ __forceinline__ void cvt_tf32(F& f) {
    #pragma unroll
    for (int i = 0; i < f.num_elements; i++) f.x[i] = wmma::__float_to_tf32(f.x[i]);
}

typedef wmma::fragment<wmma::matrix_a, 16,16,8, wmma::precision::tf32, wmma::row_major> AFrag;
typedef wmma::fragment<wmma::matrix_b, 16,16,8, wmma::precision::tf32, wmma::col_major> BFragC;
typedef wmma::fragment<wmma::matrix_b, 16,16,8, wmma::precision::tf32, wmma::row_major> BFragR;
typedef wmma::fragment<wmma::accumulator, 16,16,8, float> CFrag;

__device__ __forceinline__ void cp16(uint32_t dst, const void* src) {
    asm volatile("cp.async.cg.shared.global [%0], [%1], 16;" :: "r"(dst), "l"(src));
}

// ---------------------------------------------------------------------------
__global__ void prep_kernel(const float* __restrict__ Atw, const float* __restrict__ Atb,
                            const float* __restrict__ Acw, const float* __restrict__ Acb,
                            const float* __restrict__ Bcw, const float* __restrict__ Bcb,
                            const float* __restrict__ Rw)
{
    const int i = blockIdx.x*blockDim.x + threadIdx.x;
    const int stride = gridDim.x*blockDim.x;
    for (int idx = i; idx < 64*256; idx += stride) {
        int d = idx >> 8, e = idx & 255;
        g_Wq[idx] = (d < 60) ? Atw[d*256+e] : 0.f;
    }
    for (int idx = i; idx < 128*256; idx += stride) {
        int d = idx >> 8, e = idx & 255;
        float v = 0.f;
        if (d < 60) v = Acw[d*256+e];
        else if (d >= 64 && d < 124) v = Bcw[(d-64)*256+e];
        g_Wc[idx] = v;
    }
    for (int idx = i; idx < 256*64; idx += stride) {
        int e = idx >> 6, dv = idx & 63;
        g_Rp[idx] = (dv < 60) ? Rw[e*60+dv] : 0.f;
    }
    if (i < 64)  g_bq[i] = (i < 60) ? Atb[i] : 0.f;
    if (i < 128) g_bc[i] = (i < 60) ? Acb[i] : ((i >= 64 && i < 124) ? Bcb[i-64] : 0.f);
}

// ---------------------------------------------------------------------------
// Kernel 1: K/V projection (unchanged from R9 passing version).
// ---------------------------------------------------------------------------
#define KV_CEMB 0                    // 128 x 260
#define KV_OUT  33280                // 128 x 132
#define KV_IT   (33280+16896)        // 128 ints
#define KV_SMEM_BYTES ((33280+16896+128)*4)

__global__ __launch_bounds__(256) void kv_proj_w(
    const int* __restrict__ citems, const float* __restrict__ cvec)
{
    extern __shared__ float sm[];
    float* cemb = sm + KV_CEMB;
    float* outp = sm + KV_OUT;
    int*   items = (int*)(sm + KV_IT);

    const int t = threadIdx.x, lane = t & 31, w = t >> 5;
    const int base = blockIdx.x * 128;

    if (t < 128) items[t] = citems[base + t];
    __syncthreads();

    for (int r = w*16; r < w*16 + 16; r++) {
        const float4* src = (const float4*)(cvec + (size_t)items[r]*EMB);
        float4* dst = (float4*)(cemb + r*260);
        #pragma unroll
        for (int i = lane; i < 64; i += 32) dst[i] = src[i];
    }
    __syncthreads();

    {
        const int ma = w & 3;
        const int ng = (w >> 2) * 4;
        CFrag acc[2][4];
        #pragma unroll
        for (int m = 0; m < 2; m++)
            #pragma unroll
            for (int j = 0; j < 4; j++) wmma::fill_fragment(acc[m][j], 0.f);
        for (int k0 = 0; k0 < 256; k0 += 8) {
            AFrag a0, a1;
            wmma::load_matrix_sync(a0, cemb + ma*16*260 + k0, 260);
            wmma::load_matrix_sync(a1, cemb + (ma+4)*16*260 + k0, 260);
            cvt_tf32(a0); cvt_tf32(a1);
            #pragma unroll
            for (int j = 0; j < 4; j++) {
                BFragC bf;
                wmma::load_matrix_sync(bf, g_Wc + (size_t)(ng+j)*16*256 + k0, 256);
                cvt_tf32(bf);
                wmma::mma_sync(acc[0][j], a0, bf, acc[0][j]);
                wmma::mma_sync(acc[1][j], a1, bf, acc[1][j]);
            }
        }
        #pragma unroll
        for (int m = 0; m < 2; m++)
            #pragma unroll
            for (int j = 0; j < 4; j++)
                wmma::store_matrix_sync(outp + (ma + m*4)*16*132 + (ng+j)*16,
                                        acc[m][j], 132, wmma::mem_row_major);
    }
    __syncthreads();

    for (int idx = t; idx < 16384; idx += 256) {
        const int r = idx >> 7, c = idx & 127;
        float v = outp[r*132 + c] + g_bc[c];
        outp[r*132 + c] = v;
        if (c < 64) g_K[(size_t)(base + r)*64 + c]        = v;
        else        g_V[(size_t)(base + r)*64 + (c - 64)] = v;
    }
    __syncthreads();
    if (t < 128) {
        float s = 0.f;
        #pragma unroll 4
        for (int c = 0; c < 60; c++) { float v = outp[t*132 + c]; s += v*v; }
        g_ikn[base + t] = rsqrtf(s);
    }
}

// ---------------------------------------------------------------------------
// Kernel 2: fused attention, 128 queries/block.
// - double-buffered cp.async K/V(+kn,pb) tiles
// - warp-local score->exp->PV (1 block barrier per tile instead of 4)
// - Q fragments register-resident across the kt loop
// ---------------------------------------------------------------------------
#define AS_Q   0            // 128 x 68
#define AS_BUF 8704         // 2 buffers of BUF_SZ
#define BUF_K  0            // 64 x 68
#define BUF_V  4352         // 64 x 68
#define BUF_KN 8704         // 64
#define BUF_PB 8768         // 64
#define BUF_SZ 8832
#define AS_P   26368        // 128 x 68
#define AS_O   8704         // overlay on buffer region after kt loop (128 x 68)
#define AS_QN  35072        // 128
#define AS_L   35200        // 128
#define AS_IT  35328        // 128 ints
#define ATT_FLOATS 35456
#define ATT_SMEM_BYTES (ATT_FLOATS*4)

__device__ __forceinline__ void prefetch_tile(
    float* bufg, const float* Kg, const float* Vg,
    const float* ikng, const float* pbg, int t)
{
    uint32_t sb = (uint32_t)__cvta_generic_to_shared(bufg);
    #pragma unroll
    for (int i = 0; i < 8; i++) {
        const int idx = t + i*256;          // 0..2047
        const int r = (idx >> 4) & 63;
        const int c = (idx & 15) * 4;
        if (idx < 1024) cp16(sb + (BUF_K + r*68 + c)*4, Kg + r*64 + c);
        else            cp16(sb + (BUF_V + r*68 + c)*4, Vg + r*64 + c);
    }
    if (t < 16)      cp16(sb + (BUF_KN + t*4)*4, ikng + t*4);
    else if (t < 32) cp16(sb + (BUF_PB + (t-16)*4)*4, pbg + (t-16)*4);
}

__global__ __launch_bounds__(256) void att_w(
    const int* __restrict__ titems, const float* __restrict__ tvec,
    const float* __restrict__ pos_bias, const float* __restrict__ Rb,
    float* __restrict__ out)
{
    extern __shared__ float sm[];
    const int t = threadIdx.x, lane = t & 31, w = t >> 5;
    const int b  = blockIdx.x >> 2;
    const int qt = blockIdx.x & 3;
    const int tok0 = b*NTQ + qt*128;

    int* it_s = (int*)(sm + AS_IT);
    if (t < 128) it_s[t] = titems[tok0 + t];
    __syncthreads();

    // ---- Q projection in two 64-row halves (gather staged over buffers) ----
    float* qemb = sm + AS_BUF;   // 64 x 260 = 16640 fl < 2*BUF_SZ
    for (int h = 0; h < 2; h++) {
        for (int r = w*8; r < w*8 + 8; r++) {
            const float4* src = (const float4*)(tvec + (size_t)it_s[h*64 + r]*EMB);
            float4* dst = (float4*)(qemb + r*260);
            #pragma unroll
            for (int i = lane; i < 64; i += 32) dst[i] = src[i];
        }
        __syncthreads();
        {
            const int tm = w >> 1, tn0 = (w & 1) * 2;
            CFrag acc[2];
            wmma::fill_fragment(acc[0], 0.f);
            wmma::fill_fragment(acc[1], 0.f);
            for (int k0 = 0; k0 < 256; k0 += 8) {
                AFrag af;
                wmma::load_matrix_sync(af, qemb + tm*16*260 + k0, 260);
                cvt_tf32(af);
                #pragma unroll
                for (int u = 0; u < 2; u++) {
                    BFragC bf;
                    wmma::load_matrix_sync(bf, g_Wq + (size_t)(tn0+u)*16*256 + k0, 256);
                    cvt_tf32(bf);
                    wmma::mma_sync(acc[u], af, bf, acc[u]);
                }
            }
            #pragma unroll
            for (int u = 0; u < 2; u++)
                wmma::store_matrix_sync(sm + AS_Q + (h*64 + tm*16)*68 + (tn0+u)*16,
                                        acc[u], 68, wmma::mem_row_major);
        }
        __syncthreads();
    }
    // bias + inverse query norms + L init
    for (int idx = t; idx < 8192; idx += 256) {
        const int r = idx >> 6, c = idx & 63;
        sm[AS_Q + r*68 + c] += g_bq[c];
    }
    __syncthreads();
    if (t < 128) {
        float s = 0.f;
        #pragma unroll 4
        for (int c = 0; c < 64; c++) { float v = sm[AS_Q + t*68 + c]; s += v*v; }
        sm[AS_QN + t] = rsqrtf(s);
        sm[AS_L + t] = 0.f;
    }
    __syncthreads();

    // ---- Q fragments register-resident (rows 16w..16w+15, 8 k-steps) ----
    AFrag qf[8];
    #pragma unroll
    for (int k0 = 0; k0 < 8; k0++) {
        wmma::load_matrix_sync(qf[k0], sm + AS_Q + w*16*68 + k0*8, 68);
        cvt_tf32(qf[k0]);
    }

    // ---- prefetch tile 0 ----
    {
        const size_t gb0 = (size_t)(b*NCK) * 64;
        prefetch_tile(sm + AS_BUF, g_K + gb0, g_V + gb0,
                      g_ikn + b*NCK, pos_bias, t);
        asm volatile("cp.async.commit_group;" ::: "memory");
    }

    CFrag oacc[4];
    #pragma unroll
    for (int j = 0; j < 4; j++) wmma::fill_fragment(oacc[j], 0.f);

    for (int kt = 0; kt < 8; kt++) {
        float* buf = sm + AS_BUF + (kt & 1)*BUF_SZ;
        asm volatile("cp.async.wait_group 0;" ::: "memory");
        __syncthreads();                       // tile kt ready; prev buffer free

        if (kt < 7) {
            const size_t gb = (size_t)(b*NCK + (kt+1)*64) * 64;
            prefetch_tile(sm + AS_BUF + ((kt+1)&1)*BUF_SZ, g_K + gb, g_V + gb,
                          g_ikn + b*NCK + (kt+1)*64, pos_bias + (kt+1)*64, t);
            asm volatile("cp.async.commit_group;" ::: "memory");
        }

        // ---- scores: warp w computes P rows 16w..16w+15 (all 64 k-cols) ----
        {
            CFrag acc[4];
            #pragma unroll
            for (int j = 0; j < 4; j++) wmma::fill_fragment(acc[j], 0.f);
            #pragma unroll
            for (int k0 = 0; k0 < 8; k0++) {
                #pragma unroll
                for (int j = 0; j < 4; j++) {
                    BFragC bf;
                    wmma::load_matrix_sync(bf, buf + BUF_K + j*16*68 + k0*8, 68);
                    cvt_tf32(bf);
                    wmma::mma_sync(acc[j], qf[k0], bf, acc[j]);
                }
            }
            #pragma unroll
            for (int j = 0; j < 4; j++)
                wmma::store_matrix_sync(sm + AS_P + w*16*68 + j*16, acc[j], 68,
                                        wmma::mem_row_major);
        }
        __syncwarp();

        // ---- exp (warp-local rows) + pair-reduced denominator ----
        {
            const int q = w*16 + (lane >> 1);
            const int ha = lane & 1;
            const float iq = sm[AS_QN + q];
            float* Prow = sm + AS_P + q*68;
            const float* knp = buf + BUF_KN;
            const float* pbp = buf + BUF_PB;
            float s = 0.f;
            #pragma unroll
            for (int j = 0; j < 32; j++) {
                const int k = ha*32 + j;
                const float p = __expf(Prow[k] * (iq * knp[k]) + pbp[k]);
                Prow[k] = p;
                s += p;
            }
            s += __shfl_xor_sync(0xffffffff, s, 1);
            if (ha == 0) sm[AS_L + q] += s;
        }
        __syncwarp();

        // ---- PV accumulate (A = own P rows, warp-local) ----
        #pragma unroll
        for (int k0 = 0; k0 < 8; k0++) {
            AFrag af;
            wmma::load_matrix_sync(af, sm + AS_P + w*16*68 + k0*8, 68);
            cvt_tf32(af);
            #pragma unroll
            for (int j = 0; j < 4; j++) {
                BFragR bf;
                wmma::load_matrix_sync(bf, buf + BUF_V + k0*8*68 + j*16, 68);
                cvt_tf32(bf);
                wmma::mma_sync(oacc[j], af, bf, oacc[j]);
            }
        }
        // no bottom barrier: next iteration's top barrier covers reuse
    }
    __syncthreads();    // all warps done with buffers before O overlays them

    // ---- finalize: O = oacc / L (O overlays buffer region) ----
    #pragma unroll
    for (int j = 0; j < 4; j++)
        wmma::store_matrix_sync(sm + AS_O + w*16*68 + j*16, oacc[j], 68,
                                wmma::mem_row_major);
    __syncthreads();
    if (t < 128) sm[AS_QN + t] = 1.f / sm[AS_L + t];
    __syncthreads();
    for (int idx = t; idx < 8192; idx += 256) {
        const int r = idx >> 6, c = idx & 63;
        sm[AS_O + r*68 + c] *= sm[AS_QN + r];
    }
    __syncthreads();

    // ---- output projection: O(128x64) @ Rp^T in 4 chunks of 64 cols ----
    AFrag of[8];
    #pragma unroll
    for (int k0 = 0; k0 < 8; k0++) {
        wmma::load_matrix_sync(of[k0], sm + AS_O + w*16*68 + k0*8, 68);
        cvt_tf32(of[k0]);
    }
    for (int chunk = 0; chunk < 4; chunk++) {
        CFrag acc[4];
        #pragma unroll
        for (int j = 0; j < 4; j++) wmma::fill_fragment(acc[j], 0.f);
        #pragma unroll
        for (int k0 = 0; k0 < 8; k0++) {
            #pragma unroll
            for (int j = 0; j < 4; j++) {
                BFragC bf;
                wmma::load_matrix_sync(bf, g_Rp + (size_t)(chunk*64 + j*16)*64 + k0*8, 64);
                cvt_tf32(bf);
                wmma::mma_sync(acc[j], of[k0], bf, acc[j]);
            }
        }
        #pragma unroll
        for (int j = 0; j < 4; j++)
            wmma::store_matrix_sync(sm + AS_P + w*16*68 + j*16, acc[j], 68,
                                    wmma::mem_row_major);
        __syncthreads();
        const int e0 = chunk*64;
        for (int idx = t; idx < 8192; idx += 256) {
            const int r = idx >> 6, c = idx & 63;
            out[(size_t)(tok0 + r)*EMB + e0 + c] = sm[AS_P + r*68 + c] + Rb[e0 + c];
        }
        __syncthreads();
    }
}

// ---------------------------------------------------------------------------
extern "C" void kernel_launch(void* const* d_in, const int* in_sizes, int n_in,
                              void* d_out, int out_size)
{
    (void)in_sizes; (void)n_in; (void)out_size;
    const int*   titems = (const int*)  d_in[0];
    const int*   citems = (const int*)  d_in[1];
    const float* tvec   = (const float*)d_in[2];
    const float* cvec   = (const float*)d_in[3];
    const float* Atw    = (const float*)d_in[4];
    const float* Atb    = (const float*)d_in[5];
    const float* Acw    = (const float*)d_in[6];
    const float* Acb    = (const float*)d_in[7];
    const float* Bcw    = (const float*)d_in[8];
    const float* Bcb    = (const float*)d_in[9];
    const float* pb     = (const float*)d_in[10];
    const float* Rw     = (const float*)d_in[11];
    const float* Rb     = (const float*)d_in[12];
    float* out = (float*)d_out;

    prep_kernel<<<128, 256>>>(Atw, Atb, Acw, Acb, Bcw, Bcb, Rw);

    cudaFuncSetAttribute(kv_proj_w, cudaFuncAttributeMaxDynamicSharedMemorySize,
                         KV_SMEM_BYTES);
    kv_proj_w<<<NTOK/128, 256, KV_SMEM_BYTES>>>(citems, cvec);

    cudaFuncSetAttribute(att_w, cudaFuncAttributeMaxDynamicSharedMemorySize,
                         ATT_SMEM_BYTES);
    att_w<<<BATCH*(NTQ/128), 256, ATT_SMEM_BYTES>>>(titems, tvec, pb, Rb, out);
}

// round 12
// speedup vs baseline: 1.1194x; 1.1194x over previous
#include <cuda_runtime.h>
#include <mma.h>
#include <math.h>
#include <cstdint>

using namespace nvcuda;

#define BATCH 128
#define NTQ   512
#define NCK   512
#define EMB   256
#define NTOK  (BATCH*NCK)

// ---- device scratch (allocation-free) ----
__device__ float g_K[NTOK*64];      // K padded, tf32-pre-rounded
__device__ float g_V[NTOK*64];      // V padded, tf32-pre-rounded
__device__ float g_ikn[NTOK];       // inverse key norms
__device__ float g_Wq[64*256];      // At_w padded, tf32-pre-rounded
__device__ float g_Wc[128*256];     // [Ac_w; pad; Bc_w; pad], tf32-pre-rounded
__device__ float g_Rp[256*64];      // R_w padded, tf32-pre-rounded
__device__ float g_bq[64];
__device__ float g_bc[128];

__device__ __forceinline__ float r32(float x) { return wmma::__float_to_tf32(x); }

typedef wmma::fragment<wmma::matrix_a, 16,16,8, wmma::precision::tf32, wmma::row_major> AFrag;
typedef wmma::fragment<wmma::matrix_b, 16,16,8, wmma::precision::tf32, wmma::col_major> BFragC;
typedef wmma::fragment<wmma::matrix_b, 16,16,8, wmma::precision::tf32, wmma::row_major> BFragR;
typedef wmma::fragment<wmma::accumulator, 16,16,8, float> CFrag;

// ---------------------------------------------------------------------------
// Prep: padded weight copies, pre-rounded to tf32 so consumers skip cvt.
// ---------------------------------------------------------------------------
__global__ void prep_kernel(const float* __restrict__ Atw, const float* __restrict__ Atb,
                            const float* __restrict__ Acw, const float* __restrict__ Acb,
                            const float* __restrict__ Bcw, const float* __restrict__ Bcb,
                            const float* __restrict__ Rw)
{
    const int i = blockIdx.x*blockDim.x + threadIdx.x;
    const int stride = gridDim.x*blockDim.x;
    for (int idx = i; idx < 64*256; idx += stride) {
        int d = idx >> 8, e = idx & 255;
        g_Wq[idx] = (d < 60) ? r32(Atw[d*256+e]) : 0.f;
    }
    for (int idx = i; idx < 128*256; idx += stride) {
        int d = idx >> 8, e = idx & 255;
        float v = 0.f;
        if (d < 60) v = r32(Acw[d*256+e]);
        else if (d >= 64 && d < 124) v = r32(Bcw[(d-64)*256+e]);
        g_Wc[idx] = v;
    }
    for (int idx = i; idx < 256*64; idx += stride) {
        int e = idx >> 6, dv = idx & 63;
        g_Rp[idx] = (dv < 60) ? r32(Rw[e*60+dv]) : 0.f;
    }
    if (i < 64)  g_bq[i] = (i < 60) ? Atb[i] : 0.f;
    if (i < 128) g_bc[i] = (i < 60) ? Acb[i] : ((i >= 64 && i < 124) ? Bcb[i-64] : 0.f);
}

// ---------------------------------------------------------------------------
// Kernel 1: K/V projection. cemb rounded at gather-store; no cvt in MMA loop;
// K/V written pre-rounded.
// ---------------------------------------------------------------------------
#define KV_CEMB 0                    // 128 x 260
#define KV_OUT  33280                // 128 x 132
#define KV_IT   (33280+16896)        // 128 ints
#define KV_SMEM_BYTES ((33280+16896+128)*4)

__global__ __launch_bounds__(256) void kv_proj_w(
    const int* __restrict__ citems, const float* __restrict__ cvec)
{
    extern __shared__ float sm[];
    float* cemb = sm + KV_CEMB;
    float* outp = sm + KV_OUT;
    int*   items = (int*)(sm + KV_IT);

    const int t = threadIdx.x, lane = t & 31, w = t >> 5;
    const int base = blockIdx.x * 128;

    if (t < 128) items[t] = citems[base + t];
    __syncthreads();

    for (int r = w*16; r < w*16 + 16; r++) {
        const float4* src = (const float4*)(cvec + (size_t)items[r]*EMB);
        float4* dst = (float4*)(cemb + r*260);
        #pragma unroll
        for (int i = lane; i < 64; i += 32) {
            float4 v = src[i];
            v.x = r32(v.x); v.y = r32(v.y); v.z = r32(v.z); v.w = r32(v.w);
            dst[i] = v;
        }
    }
    __syncthreads();

    {
        const int ma = w & 3;
        const int ng = (w >> 2) * 4;
        CFrag acc[2][4];
        #pragma unroll
        for (int m = 0; m < 2; m++)
            #pragma unroll
            for (int j = 0; j < 4; j++) wmma::fill_fragment(acc[m][j], 0.f);
        for (int k0 = 0; k0 < 256; k0 += 8) {
            AFrag a0, a1;
            wmma::load_matrix_sync(a0, cemb + ma*16*260 + k0, 260);
            wmma::load_matrix_sync(a1, cemb + (ma+4)*16*260 + k0, 260);
            #pragma unroll
            for (int j = 0; j < 4; j++) {
                BFragC bf;
                wmma::load_matrix_sync(bf, g_Wc + (size_t)(ng+j)*16*256 + k0, 256);
                wmma::mma_sync(acc[0][j], a0, bf, acc[0][j]);
                wmma::mma_sync(acc[1][j], a1, bf, acc[1][j]);
            }
        }
        #pragma unroll
        for (int m = 0; m < 2; m++)
            #pragma unroll
            for (int j = 0; j < 4; j++)
                wmma::store_matrix_sync(outp + (ma + m*4)*16*132 + (ng+j)*16,
                                        acc[m][j], 132, wmma::mem_row_major);
    }
    __syncthreads();

    for (int idx = t; idx < 16384; idx += 256) {
        const int r = idx >> 7, c = idx & 127;
        float v = r32(outp[r*132 + c] + g_bc[c]);   // pre-round for att consumers
        outp[r*132 + c] = v;
        if (c < 64) g_K[(size_t)(base + r)*64 + c]        = v;
        else        g_V[(size_t)(base + r)*64 + (c - 64)] = v;
    }
    __syncthreads();
    if (t < 128) {
        float s = 0.f;
        #pragma unroll 4
        for (int c = 0; c < 60; c++) { float v = outp[t*132 + c]; s += v*v; }
        g_ikn[base + t] = rsqrtf(s);
    }
}

// ---------------------------------------------------------------------------
// Kernel 2: fused attention. 128 q/block, single K/V buffer (2 CTAs/SM),
// warp-local score->exp->PV (2 block barriers/tile), reg-resident Q frags,
// zero cvt in all MMA loops (operands pre-rounded).
// ---------------------------------------------------------------------------
#define AS_Q   0            // 128 x 68 = 8704
#define BUF_K  8704         // 64 x 68
#define BUF_V  13056        // 64 x 68
#define S_KN   17408        // 64
#define S_PB   17472        // 64
#define AS_P   17536        // 128 x 68 -> ends 26240
#define AS_O   8704         // overlay on BUF_K+BUF_V after kt loop (128 x 68)
#define AS_QN  26240        // 128
#define AS_L   26368        // 128
#define AS_IT  26496        // 128 ints
#define ATT_FLOATS 26624    // 106,496 B -> 2 CTAs/SM
#define ATT_SMEM_BYTES (ATT_FLOATS*4)

__global__ __launch_bounds__(256, 2) void att_w(
    const int* __restrict__ titems, const float* __restrict__ tvec,
    const float* __restrict__ pos_bias, const float* __restrict__ Rb,
    float* __restrict__ out)
{
    extern __shared__ float sm[];
    const int t = threadIdx.x, lane = t & 31, w = t >> 5;
    const int b  = blockIdx.x >> 2;
    const int qt = blockIdx.x & 3;
    const int tok0 = b*NTQ + qt*128;

    int* it_s = (int*)(sm + AS_IT);
    if (t < 128) it_s[t] = titems[tok0 + t];
    __syncthreads();

    // ---- Q projection in two 64-row halves (gather staged over BUF..P) ----
    float* qemb = sm + BUF_K;   // 64 x 260 = 16640 fl, fits in [8704, 26240)
    for (int h = 0; h < 2; h++) {
        for (int r = w*8; r < w*8 + 8; r++) {
            const float4* src = (const float4*)(tvec + (size_t)it_s[h*64 + r]*EMB);
            float4* dst = (float4*)(qemb + r*260);
            #pragma unroll
            for (int i = lane; i < 64; i += 32) {
                float4 v = src[i];
                v.x = r32(v.x); v.y = r32(v.y); v.z = r32(v.z); v.w = r32(v.w);
                dst[i] = v;
            }
        }
        __syncthreads();
        {
            const int tm = w >> 1, tn0 = (w & 1) * 2;
            CFrag acc[2];
            wmma::fill_fragment(acc[0], 0.f);
            wmma::fill_fragment(acc[1], 0.f);
            for (int k0 = 0; k0 < 256; k0 += 8) {
                AFrag af;
                wmma::load_matrix_sync(af, qemb + tm*16*260 + k0, 260);
                #pragma unroll
                for (int u = 0; u < 2; u++) {
                    BFragC bf;
                    wmma::load_matrix_sync(bf, g_Wq + (size_t)(tn0+u)*16*256 + k0, 256);
                    wmma::mma_sync(acc[u], af, bf, acc[u]);
                }
            }
            #pragma unroll
            for (int u = 0; u < 2; u++)
                wmma::store_matrix_sync(sm + AS_Q + (h*64 + tm*16)*68 + (tn0+u)*16,
                                        acc[u], 68, wmma::mem_row_major);
        }
        __syncthreads();
    }
    // bias + pre-round Q; inverse query norms; L init
    for (int idx = t; idx < 8192; idx += 256) {
        const int r = idx >> 6, c = idx & 63;
        sm[AS_Q + r*68 + c] = r32(sm[AS_Q + r*68 + c] + g_bq[c]);
    }
    __syncthreads();
    if (t < 128) {
        float s = 0.f;
        #pragma unroll 4
        for (int c = 0; c < 64; c++) { float v = sm[AS_Q + t*68 + c]; s += v*v; }
        sm[AS_QN + t] = rsqrtf(s);
        sm[AS_L + t] = 0.f;
    }
    __syncthreads();

    // ---- Q fragments register-resident (rows 16w..16w+15, pre-rounded) ----
    AFrag qf[8];
    #pragma unroll
    for (int k0 = 0; k0 < 8; k0++)
        wmma::load_matrix_sync(qf[k0], sm + AS_Q + w*16*68 + k0*8, 68);

    CFrag oacc[4];
    #pragma unroll
    for (int j = 0; j < 4; j++) wmma::fill_fragment(oacc[j], 0.f);

    for (int kt = 0; kt < 8; kt++) {
        // ---- load K/V tile (synchronous, float4) ----
        {
            const size_t gb = (size_t)(b*NCK + kt*64) * 64;
            const float4* Ksrc = (const float4*)(g_K + gb);
            const float4* Vsrc = (const float4*)(g_V + gb);
            #pragma unroll
            for (int i = 0; i < 4; i++) {
                const int idx = t + i*256;          // 0..1023
                const int r = idx >> 4, c = (idx & 15) * 4;
                *(float4*)(sm + BUF_K + r*68 + c) = Ksrc[idx];
                *(float4*)(sm + BUF_V + r*68 + c) = Vsrc[idx];
            }
            if (t < 64) {
                sm[S_KN + t] = g_ikn[b*NCK + kt*64 + t];
                sm[S_PB + t] = pos_bias[kt*64 + t];
            }
        }
        __syncthreads();

        // ---- scores: warp w computes P rows 16w..16w+15 ----
        {
            CFrag acc[4];
            #pragma unroll
            for (int j = 0; j < 4; j++) wmma::fill_fragment(acc[j], 0.f);
            #pragma unroll
            for (int k0 = 0; k0 < 8; k0++) {
                #pragma unroll
                for (int j = 0; j < 4; j++) {
                    BFragC bf;
                    wmma::load_matrix_sync(bf, sm + BUF_K + j*16*68 + k0*8, 68);
                    wmma::mma_sync(acc[j], qf[k0], bf, acc[j]);
                }
            }
            #pragma unroll
            for (int j = 0; j < 4; j++)
                wmma::store_matrix_sync(sm + AS_P + w*16*68 + j*16, acc[j], 68,
                                        wmma::mem_row_major);
        }
        __syncwarp();

        // ---- exp (warp-owned rows), store tf32-rounded P, accumulate L ----
        {
            const int q = w*16 + (lane >> 1);
            const int ha = lane & 1;
            const float iq = sm[AS_QN + q];
            float* Prow = sm + AS_P + q*68;
            float s = 0.f;
            #pragma unroll
            for (int j = 0; j < 32; j++) {
                const int k = ha*32 + j;
                const float p = r32(__expf(Prow[k] * (iq * sm[S_KN + k]) + sm[S_PB + k]));
                Prow[k] = p;
                s += p;
            }
            s += __shfl_xor_sync(0xffffffff, s, 1);
            if (ha == 0) sm[AS_L + q] += s;
        }
        __syncwarp();

        // ---- PV accumulate (A = own P rows, pre-rounded) ----
        #pragma unroll
        for (int k0 = 0; k0 < 8; k0++) {
            AFrag af;
            wmma::load_matrix_sync(af, sm + AS_P + w*16*68 + k0*8, 68);
            #pragma unroll
            for (int j = 0; j < 4; j++) {
                BFragR bf;
                wmma::load_matrix_sync(bf, sm + BUF_V + k0*8*68 + j*16, 68);
                wmma::mma_sync(oacc[j], af, bf, oacc[j]);
            }
        }
        __syncthreads();    // PV done before next tile overwrites K/V
    }

    // ---- finalize: O = oacc / L, pre-round (O overlays BUF region) ----
    #pragma unroll
    for (int j = 0; j < 4; j++)
        wmma::store_matrix_sync(sm + AS_O + w*16*68 + j*16, oacc[j], 68,
                                wmma::mem_row_major);
    __syncthreads();
    if (t < 128) sm[AS_QN + t] = 1.f / sm[AS_L + t];
    __syncthreads();
    for (int idx = t; idx < 8192; idx += 256) {
        const int r = idx >> 6, c = idx & 63;
        sm[AS_O + r*68 + c] = r32(sm[AS_O + r*68 + c] * sm[AS_QN + r]);
    }
    __syncthreads();

    // ---- output projection: O(128x64) @ Rp^T in 4 chunks of 64 cols ----
    AFrag of[8];
    #pragma unroll
    for (int k0 = 0; k0 < 8; k0++)
        wmma::load_matrix_sync(of[k0], sm + AS_O + w*16*68 + k0*8, 68);
    for (int chunk = 0; chunk < 4; chunk++) {
        CFrag acc[4];
        #pragma unroll
        for (int j = 0; j < 4; j++) wmma::fill_fragment(acc[j], 0.f);
        #pragma unroll
        for (int k0 = 0; k0 < 8; k0++) {
            #pragma unroll
            for (int j = 0; j < 4; j++) {
                BFragC bf;
                wmma::load_matrix_sync(bf, g_Rp + (size_t)(chunk*64 + j*16)*64 + k0*8, 64);
                wmma::mma_sync(acc[j], of[k0], bf, acc[j]);
            }
        }
        #pragma unroll
        for (int j = 0; j < 4; j++)
            wmma::store_matrix_sync(sm + AS_P + w*16*68 + j*16, acc[j], 68,
                                    wmma::mem_row_major);
        __syncthreads();
        const int e0 = chunk*64;
        for (int idx = t; idx < 8192; idx += 256) {
            const int r = idx >> 6, c = idx & 63;
            out[(size_t)(tok0 + r)*EMB + e0 + c] = sm[AS_P + r*68 + c] + Rb[e0 + c];
        }
        __syncthreads();
    }
}

// ---------------------------------------------------------------------------
extern "C" void kernel_launch(void* const* d_in, const int* in_sizes, int n_in,
                              void* d_out, int out_size)
{
    (void)in_sizes; (void)n_in; (void)out_size;
    const int*   titems = (const int*)  d_in[0];
    const int*   citems = (const int*)  d_in[1];
    const float* tvec   = (const float*)d_in[2];
    const float* cvec   = (const float*)d_in[3];
    const float* Atw    = (const float*)d_in[4];
    const float* Atb    = (const float*)d_in[5];
    const float* Acw    = (const float*)d_in[6];
    const float* Acb    = (const float*)d_in[7];
    const float* Bcw    = (const float*)d_in[8];
    const float* Bcb    = (const float*)d_in[9];
    const float* pb     = (const float*)d_in[10];
    const float* Rw     = (const float*)d_in[11];
    const float* Rb     = (const float*)d_in[12];
    float* out = (float*)d_out;

    prep_kernel<<<128, 256>>>(Atw, Atb, Acw, Acb, Bcw, Bcb, Rw);

    cudaFuncSetAttribute(kv_proj_w, cudaFuncAttributeMaxDynamicSharedMemorySize,
                         KV_SMEM_BYTES);
    kv_proj_w<<<NTOK/128, 256, KV_SMEM_BYTES>>>(citems, cvec);

    cudaFuncSetAttribute(att_w, cudaFuncAttributeMaxDynamicSharedMemorySize,
                         ATT_SMEM_BYTES);
    att_w<<<BATCH*(NTQ/128), 256, ATT_SMEM_BYTES>>>(titems, tvec, pb, Rb, out);
}

// round 14
// speedup vs baseline: 1.1707x; 1.0458x over previous
#include <cuda_runtime.h>
#include <mma.h>
#include <math.h>
#include <cstdint>

using namespace nvcuda;

#define BATCH 128
#define NTQ   512
#define NCK   512
#define EMB   256
#define NTOK  (BATCH*NCK)

// ---- device scratch (allocation-free) ----
__device__ float g_K[NTOK*64];      // K padded, tf32-pre-rounded
__device__ float g_V[NTOK*64];      // V padded, tf32-pre-rounded
__device__ float g_ikn[NTOK];       // inverse key norms
__device__ float g_Wq[64*256];      // At_w padded, tf32-pre-rounded
__device__ float g_Wc[128*256];     // [Ac_w; pad; Bc_w; pad], tf32-pre-rounded
__device__ float g_Rp[256*64];      // R_w padded, tf32-pre-rounded
__device__ float g_bq[64];
__device__ float g_bc[128];

__device__ __forceinline__ float r32(float x) { return wmma::__float_to_tf32(x); }

typedef wmma::fragment<wmma::matrix_a, 16,16,8, wmma::precision::tf32, wmma::row_major> AFrag;
typedef wmma::fragment<wmma::matrix_b, 16,16,8, wmma::precision::tf32, wmma::col_major> BFragC;
typedef wmma::fragment<wmma::matrix_b, 16,16,8, wmma::precision::tf32, wmma::row_major> BFragR;
typedef wmma::fragment<wmma::accumulator, 16,16,8, float> CFrag;

// ---------------------------------------------------------------------------
__global__ void prep_kernel(const float* __restrict__ Atw, const float* __restrict__ Atb,
                            const float* __restrict__ Acw, const float* __restrict__ Acb,
                            const float* __restrict__ Bcw, const float* __restrict__ Bcb,
                            const float* __restrict__ Rw)
{
    const int i = blockIdx.x*blockDim.x + threadIdx.x;
    const int stride = gridDim.x*blockDim.x;
    for (int idx = i; idx < 64*256; idx += stride) {
        int d = idx >> 8, e = idx & 255;
        g_Wq[idx] = (d < 60) ? r32(Atw[d*256+e]) : 0.f;
    }
    for (int idx = i; idx < 128*256; idx += stride) {
        int d = idx >> 8, e = idx & 255;
        float v = 0.f;
        if (d < 60) v = r32(Acw[d*256+e]);
        else if (d >= 64 && d < 124) v = r32(Bcw[(d-64)*256+e]);
        g_Wc[idx] = v;
    }
    for (int idx = i; idx < 256*64; idx += stride) {
        int e = idx >> 6, dv = idx & 63;
        g_Rp[idx] = (dv < 60) ? r32(Rw[e*60+dv]) : 0.f;
    }
    if (i < 64)  g_bq[i] = (i < 60) ? Atb[i] : 0.f;
    if (i < 128) g_bc[i] = (i < 60) ? Acb[i] : ((i >= 64 && i < 124) ? Bcb[i-64] : 0.f);
}

// ---------------------------------------------------------------------------
// Kernel 1: K/V projection. 64 tokens/block (2 CTAs/SM for latency hiding),
// 1024 blocks, 256 threads. Warp = (m-tile w&3 of 4, n-group (w>>2)*4 of 8).
// ---------------------------------------------------------------------------
#define KV_CEMB 0                    // 64 x 260 = 16640
#define KV_OUT  16640                // 64 x 132 = 8448
#define KV_IT   (16640+8448)         // 64 ints
#define KV_FLOATS (16640+8448+64)    // 25152 fl = 100.6 KB -> 2 CTAs/SM
#define KV_SMEM_BYTES (KV_FLOATS*4)

__global__ __launch_bounds__(256, 2) void kv_proj_w(
    const int* __restrict__ citems, const float* __restrict__ cvec)
{
    extern __shared__ float sm[];
    float* cemb = sm + KV_CEMB;
    float* outp = sm + KV_OUT;
    int*   items = (int*)(sm + KV_IT);

    const int t = threadIdx.x, lane = t & 31, w = t >> 5;
    const int base = blockIdx.x * 64;

    if (t < 64) items[t] = citems[base + t];
    __syncthreads();

    for (int r = w*8; r < w*8 + 8; r++) {
        const float4* src = (const float4*)(cvec + (size_t)items[r]*EMB);
        float4* dst = (float4*)(cemb + r*260);
        #pragma unroll
        for (int i = lane; i < 64; i += 32) {
            float4 v = src[i];
            v.x = r32(v.x); v.y = r32(v.y); v.z = r32(v.z); v.w = r32(v.w);
            dst[i] = v;
        }
    }
    __syncthreads();

    {
        const int ma = w & 3;            // m-tile (16 tokens)
        const int ng = (w >> 2) * 4;     // n-tiles ng..ng+3
        CFrag acc[4];
        #pragma unroll
        for (int j = 0; j < 4; j++) wmma::fill_fragment(acc[j], 0.f);
        for (int k0 = 0; k0 < 256; k0 += 8) {
            AFrag af;
            wmma::load_matrix_sync(af, cemb + ma*16*260 + k0, 260);
            #pragma unroll
            for (int j = 0; j < 4; j++) {
                BFragC bf;
                wmma::load_matrix_sync(bf, g_Wc + (size_t)(ng+j)*16*256 + k0, 256);
                wmma::mma_sync(acc[j], af, bf, acc[j]);
            }
        }
        #pragma unroll
        for (int j = 0; j < 4; j++)
            wmma::store_matrix_sync(outp + ma*16*132 + (ng+j)*16, acc[j], 132,
                                    wmma::mem_row_major);
    }
    __syncthreads();

    for (int idx = t; idx < 8192; idx += 256) {
        const int r = idx >> 7, c = idx & 127;
        float v = r32(outp[r*132 + c] + g_bc[c]);
        outp[r*132 + c] = v;
        if (c < 64) g_K[(size_t)(base + r)*64 + c]        = v;
        else        g_V[(size_t)(base + r)*64 + (c - 64)] = v;
    }
    __syncthreads();
    if (t < 64) {
        float s = 0.f;
        #pragma unroll 4
        for (int c = 0; c < 60; c++) { float v = outp[t*132 + c]; s += v*v; }
        g_ikn[base + t] = rsqrtf(s);
    }
}

// ---------------------------------------------------------------------------
// Kernel 2: fused attention. 128 q/block, 2 CTAs/SM, warp-local inner loop,
// zero cvt; out-proj Rp chunks staged through dead AS_Q smem.
// ---------------------------------------------------------------------------
#define AS_Q   0            // 128 x 68 = 8704  (dead after kt loop -> Rp stage)
#define BUF_K  8704         // 64 x 68
#define BUF_V  13056        // 64 x 68
#define S_KN   17408        // 64
#define S_PB   17472        // 64
#define AS_P   17536        // 128 x 68 -> ends 26240
#define AS_O   8704         // overlay on BUF region after kt loop (128 x 68)
#define AS_RW  0            // Rp chunk stage: 64 x 68 (overlays dead AS_Q)
#define AS_QN  26240        // 128
#define AS_L   26368        // 128
#define AS_IT  26496        // 128 ints
#define ATT_FLOATS 26624    // 106,496 B -> 2 CTAs/SM
#define ATT_SMEM_BYTES (ATT_FLOATS*4)

__global__ __launch_bounds__(256, 2) void att_w(
    const int* __restrict__ titems, const float* __restrict__ tvec,
    const float* __restrict__ pos_bias, const float* __restrict__ Rb,
    float* __restrict__ out)
{
    extern __shared__ float sm[];
    const int t = threadIdx.x, lane = t & 31, w = t >> 5;
    const int b  = blockIdx.x >> 2;
    const int qt = blockIdx.x & 3;
    const int tok0 = b*NTQ + qt*128;

    int* it_s = (int*)(sm + AS_IT);
    if (t < 128) it_s[t] = titems[tok0 + t];
    __syncthreads();

    // ---- Q projection in two 64-row halves (gather staged over BUF..P) ----
    float* qemb = sm + BUF_K;   // 64 x 260 = 16640 fl, fits in [8704, 26240)
    for (int h = 0; h < 2; h++) {
        for (int r = w*8; r < w*8 + 8; r++) {
            const float4* src = (const float4*)(tvec + (size_t)it_s[h*64 + r]*EMB);
            float4* dst = (float4*)(qemb + r*260);
            #pragma unroll
            for (int i = lane; i < 64; i += 32) {
                float4 v = src[i];
                v.x = r32(v.x); v.y = r32(v.y); v.z = r32(v.z); v.w = r32(v.w);
                dst[i] = v;
            }
        }
        __syncthreads();
        {
            const int tm = w >> 1, tn0 = (w & 1) * 2;
            CFrag acc[2];
            wmma::fill_fragment(acc[0], 0.f);
            wmma::fill_fragment(acc[1], 0.f);
            for (int k0 = 0; k0 < 256; k0 += 8) {
                AFrag af;
                wmma::load_matrix_sync(af, qemb + tm*16*260 + k0, 260);
                #pragma unroll
                for (int u = 0; u < 2; u++) {
                    BFragC bf;
                    wmma::load_matrix_sync(bf, g_Wq + (size_t)(tn0+u)*16*256 + k0, 256);
                    wmma::mma_sync(acc[u], af, bf, acc[u]);
                }
            }
            #pragma unroll
            for (int u = 0; u < 2; u++)
                wmma::store_matrix_sync(sm + AS_Q + (h*64 + tm*16)*68 + (tn0+u)*16,
                                        acc[u], 68, wmma::mem_row_major);
        }
        __syncthreads();
    }
    // bias + pre-round Q; inverse query norms; L init
    for (int idx = t; idx < 8192; idx += 256) {
        const int r = idx >> 6, c = idx & 63;
        sm[AS_Q + r*68 + c] = r32(sm[AS_Q + r*68 + c] + g_bq[c]);
    }
    __syncthreads();
    if (t < 128) {
        float s = 0.f;
        #pragma unroll 4
        for (int c = 0; c < 64; c++) { float v = sm[AS_Q + t*68 + c]; s += v*v; }
        sm[AS_QN + t] = rsqrtf(s);
        sm[AS_L + t] = 0.f;
    }
    __syncthreads();

    // ---- Q fragments register-resident (rows 16w..16w+15, pre-rounded) ----
    AFrag qf[8];
    #pragma unroll
    for (int k0 = 0; k0 < 8; k0++)
        wmma::load_matrix_sync(qf[k0], sm + AS_Q + w*16*68 + k0*8, 68);

    CFrag oacc[4];
    #pragma unroll
    for (int j = 0; j < 4; j++) wmma::fill_fragment(oacc[j], 0.f);

    for (int kt = 0; kt < 8; kt++) {
        // ---- load K/V tile (synchronous, float4) ----
        {
            const size_t gb = (size_t)(b*NCK + kt*64) * 64;
            const float4* Ksrc = (const float4*)(g_K + gb);
            const float4* Vsrc = (const float4*)(g_V + gb);
            #pragma unroll
            for (int i = 0; i < 4; i++) {
                const int idx = t + i*256;          // 0..1023
                const int r = idx >> 4, c = (idx & 15) * 4;
                *(float4*)(sm + BUF_K + r*68 + c) = Ksrc[idx];
                *(float4*)(sm + BUF_V + r*68 + c) = Vsrc[idx];
            }
            if (t < 64) {
                sm[S_KN + t] = g_ikn[b*NCK + kt*64 + t];
                sm[S_PB + t] = pos_bias[kt*64 + t];
            }
        }
        __syncthreads();

        // ---- scores: warp w computes P rows 16w..16w+15 ----
        {
            CFrag acc[4];
            #pragma unroll
            for (int j = 0; j < 4; j++) wmma::fill_fragment(acc[j], 0.f);
            #pragma unroll
            for (int k0 = 0; k0 < 8; k0++) {
                #pragma unroll
                for (int j = 0; j < 4; j++) {
                    BFragC bf;
                    wmma::load_matrix_sync(bf, sm + BUF_K + j*16*68 + k0*8, 68);
                    wmma::mma_sync(acc[j], qf[k0], bf, acc[j]);
                }
            }
            #pragma unroll
            for (int j = 0; j < 4; j++)
                wmma::store_matrix_sync(sm + AS_P + w*16*68 + j*16, acc[j], 68,
                                        wmma::mem_row_major);
        }
        __syncwarp();

        // ---- exp (warp-owned rows), store tf32-rounded P, accumulate L ----
        {
            const int q = w*16 + (lane >> 1);
            const int ha = lane & 1;
            const float iq = sm[AS_QN + q];
            float* Prow = sm + AS_P + q*68;
            float s = 0.f;
            #pragma unroll
            for (int j = 0; j < 32; j++) {
                const int k = ha*32 + j;
                const float p = r32(__expf(Prow[k] * (iq * sm[S_KN + k]) + sm[S_PB + k]));
                Prow[k] = p;
                s += p;
            }
            s += __shfl_xor_sync(0xffffffff, s, 1);
            if (ha == 0) sm[AS_L + q] += s;
        }
        __syncwarp();

        // ---- PV accumulate (A = own P rows, pre-rounded) ----
        #pragma unroll
        for (int k0 = 0; k0 < 8; k0++) {
            AFrag af;
            wmma::load_matrix_sync(af, sm + AS_P + w*16*68 + k0*8, 68);
            #pragma unroll
            for (int j = 0; j < 4; j++) {
                BFragR bf;
                wmma::load_matrix_sync(bf, sm + BUF_V + k0*8*68 + j*16, 68);
                wmma::mma_sync(oacc[j], af, bf, oacc[j]);
            }
        }
        __syncthreads();    // PV done before next tile overwrites K/V
    }

    // ---- finalize: O = oacc / L, pre-round (O overlays BUF region) ----
    #pragma unroll
    for (int j = 0; j < 4; j++)
        wmma::store_matrix_sync(sm + AS_O + w*16*68 + j*16, oacc[j], 68,
                                wmma::mem_row_major);
    __syncthreads();
    if (t < 128) sm[AS_QN + t] = 1.f / sm[AS_L + t];
    __syncthreads();
    for (int idx = t; idx < 8192; idx += 256) {
        const int r = idx >> 6, c = idx & 63;
        sm[AS_O + r*68 + c] = r32(sm[AS_O + r*68 + c] * sm[AS_QN + r]);
    }
    __syncthreads();

    // ---- output projection: O(128x64) @ Rp^T in 4 chunks of 64 cols.
    //      Rp chunk (64x64) staged through dead AS_Q region (ld 68). ----
    AFrag of[8];
    #pragma unroll
    for (int k0 = 0; k0 < 8; k0++)
        wmma::load_matrix_sync(of[k0], sm + AS_O + w*16*68 + k0*8, 68);
    for (int chunk = 0; chunk < 4; chunk++) {
        // stage g_Rp rows [chunk*64, +64), 64 cols -> AS_RW [64][68]
        {
            const float4* Rsrc = (const float4*)(g_Rp + (size_t)chunk*64*64);
            #pragma unroll
            for (int i = 0; i < 4; i++) {
                const int idx = t + i*256;          // 0..1023 float4
                const int r = idx >> 4, c = (idx & 15) * 4;
                *(float4*)(sm + AS_RW + r*68 + c) = Rsrc[idx];
            }
        }
        __syncthreads();

        CFrag acc[4];
        #pragma unroll
        for (int j = 0; j < 4; j++) wmma::fill_fragment(acc[j], 0.f);
        #pragma unroll
        for (int k0 = 0; k0 < 8; k0++) {
            #pragma unroll
            for (int j = 0; j < 4; j++) {
                BFragC bf;
                wmma::load_matrix_sync(bf, sm + AS_RW + j*16*68 + k0*8, 68);
                wmma::mma_sync(acc[j], of[k0], bf, acc[j]);
            }
        }
        #pragma unroll
        for (int j = 0; j < 4; j++)
            wmma::store_matrix_sync(sm + AS_P + w*16*68 + j*16, acc[j], 68,
                                    wmma::mem_row_major);
        __syncthreads();
        const int e0 = chunk*64;
        for (int idx = t; idx < 8192; idx += 256) {
            const int r = idx >> 6, c = idx & 63;
            out[(size_t)(tok0 + r)*EMB + e0 + c] = sm[AS_P + r*68 + c] + Rb[e0 + c];
        }
        __syncthreads();
    }
}

// ---------------------------------------------------------------------------
extern "C" void kernel_launch(void* const* d_in, const int* in_sizes, int n_in,
                              void* d_out, int out_size)
{
    (void)in_sizes; (void)n_in; (void)out_size;
    const int*   titems = (const int*)  d_in[0];
    const int*   citems = (const int*)  d_in[1];
    const float* tvec   = (const float*)d_in[2];
    const float* cvec   = (const float*)d_in[3];
    const float* Atw    = (const float*)d_in[4];
    const float* Atb    = (const float*)d_in[5];
    const float* Acw    = (const float*)d_in[6];
    const float* Acb    = (const float*)d_in[7];
    const float* Bcw    = (const float*)d_in[8];
    const float* Bcb    = (const float*)d_in[9];
    const float* pb     = (const float*)d_in[10];
    const float* Rw     = (const float*)d_in[11];
    const float* Rb     = (const float*)d_in[12];
    float* out = (float*)d_out;

    prep_kernel<<<128, 256>>>(Atw, Atb, Acw, Acb, Bcw, Bcb, Rw);

    cudaFuncSetAttribute(kv_proj_w, cudaFuncAttributeMaxDynamicSharedMemorySize,
                         KV_SMEM_BYTES);
    kv_proj_w<<<NTOK/64, 256, KV_SMEM_BYTES>>>(citems, cvec);

    cudaFuncSetAttribute(att_w, cudaFuncAttributeMaxDynamicSharedMemorySize,
                         ATT_SMEM_BYTES);
    att_w<<<BATCH*(NTQ/128), 256, ATT_SMEM_BYTES>>>(titems, tvec, pb, Rb, out);
}

// round 15
// speedup vs baseline: 1.3640x; 1.1652x over previous
#include <cuda_runtime.h>
#include <mma.h>
#include <math.h>
#include <cstdint>

using namespace nvcuda;

#define BATCH 128
#define NTQ   512
#define NCK   512
#define EMB   256
#define NTOK  (BATCH*NCK)

// ---- device scratch (allocation-free) ----
__device__ float g_K[NTOK*64];      // K padded, tf32-pre-rounded
__device__ float g_V[NTOK*64];      // V padded, tf32-pre-rounded
__device__ float g_ikn[NTOK];       // inverse key norms
__device__ float g_Wq[64*256];      // At_w padded, tf32-pre-rounded
__device__ float g_Wc[128*256];     // [Ac_w; pad; Bc_w; pad], tf32-pre-rounded
__device__ float g_Rp[256*64];      // R_w padded, tf32-pre-rounded
__device__ float g_bq[64];
__device__ float g_bc[128];

__device__ __forceinline__ float r32(float x) { return wmma::__float_to_tf32(x); }

typedef wmma::fragment<wmma::matrix_a, 16,16,8, wmma::precision::tf32, wmma::row_major> AFrag;
typedef wmma::fragment<wmma::matrix_b, 16,16,8, wmma::precision::tf32, wmma::col_major> BFragC;
typedef wmma::fragment<wmma::matrix_b, 16,16,8, wmma::precision::tf32, wmma::row_major> BFragR;
typedef wmma::fragment<wmma::accumulator, 16,16,8, float> CFrag;

// ---------------------------------------------------------------------------
__global__ void prep_kernel(const float* __restrict__ Atw, const float* __restrict__ Atb,
                            const float* __restrict__ Acw, const float* __restrict__ Acb,
                            const float* __restrict__ Bcw, const float* __restrict__ Bcb,
                            const float* __restrict__ Rw)
{
    const int i = blockIdx.x*blockDim.x + threadIdx.x;
    const int stride = gridDim.x*blockDim.x;
    for (int idx = i; idx < 64*256; idx += stride) {
        int d = idx >> 8, e = idx & 255;
        g_Wq[idx] = (d < 60) ? r32(Atw[d*256+e]) : 0.f;
    }
    for (int idx = i; idx < 128*256; idx += stride) {
        int d = idx >> 8, e = idx & 255;
        float v = 0.f;
        if (d < 60) v = r32(Acw[d*256+e]);
        else if (d >= 64 && d < 124) v = r32(Bcw[(d-64)*256+e]);
        g_Wc[idx] = v;
    }
    for (int idx = i; idx < 256*64; idx += stride) {
        int e = idx >> 6, dv = idx & 63;
        g_Rp[idx] = (dv < 60) ? r32(Rw[e*60+dv]) : 0.f;
    }
    if (i < 64)  g_bq[i] = (i < 60) ? Atb[i] : 0.f;
    if (i < 128) g_bc[i] = (i < 60) ? Acb[i] : ((i >= 64 && i < 124) ? Bcb[i-64] : 0.f);
}

// ---------------------------------------------------------------------------
// Kernel 1: K/V projection. 64 tokens/block, 2 CTAs/SM, 1024 blocks.
// NEW warp map: warp w owns n-tile w (1x), iterates all 4 m-tiles.
// g_Wc fragment redundancy 4x -> 1x.
// ---------------------------------------------------------------------------
#define KV_CEMB 0                    // 64 x 260 = 16640
#define KV_OUT  16640                // 64 x 132 = 8448
#define KV_IT   (16640+8448)         // 64 ints
#define KV_FLOATS (16640+8448+64)    // 25152 fl = 100.6 KB -> 2 CTAs/SM
#define KV_SMEM_BYTES (KV_FLOATS*4)

__global__ __launch_bounds__(256, 2) void kv_proj_w(
    const int* __restrict__ citems, const float* __restrict__ cvec)
{
    extern __shared__ float sm[];
    float* cemb = sm + KV_CEMB;
    float* outp = sm + KV_OUT;
    int*   items = (int*)(sm + KV_IT);

    const int t = threadIdx.x, lane = t & 31, w = t >> 5;
    const int base = blockIdx.x * 64;

    if (t < 64) items[t] = citems[base + t];
    __syncthreads();

    for (int r = w*8; r < w*8 + 8; r++) {
        const float4* src = (const float4*)(cvec + (size_t)items[r]*EMB);
        float4* dst = (float4*)(cemb + r*260);
        #pragma unroll
        for (int i = lane; i < 64; i += 32) {
            float4 v = src[i];
            v.x = r32(v.x); v.y = r32(v.y); v.z = r32(v.z); v.w = r32(v.w);
            dst[i] = v;
        }
    }
    __syncthreads();

    {
        const int nt = w;                // n-tile 0..7 (one per warp)
        CFrag acc[4];
        #pragma unroll
        for (int m = 0; m < 4; m++) wmma::fill_fragment(acc[m], 0.f);
        for (int k0 = 0; k0 < 256; k0 += 8) {
            BFragC bf;
            wmma::load_matrix_sync(bf, g_Wc + (size_t)nt*16*256 + k0, 256);
            #pragma unroll
            for (int m = 0; m < 4; m++) {
                AFrag af;
                wmma::load_matrix_sync(af, cemb + m*16*260 + k0, 260);
                wmma::mma_sync(acc[m], af, bf, acc[m]);
            }
        }
        #pragma unroll
        for (int m = 0; m < 4; m++)
            wmma::store_matrix_sync(outp + m*16*132 + nt*16, acc[m], 132,
                                    wmma::mem_row_major);
    }
    __syncthreads();

    for (int idx = t; idx < 8192; idx += 256) {
        const int r = idx >> 7, c = idx & 127;
        float v = r32(outp[r*132 + c] + g_bc[c]);
        outp[r*132 + c] = v;
        if (c < 64) g_K[(size_t)(base + r)*64 + c]        = v;
        else        g_V[(size_t)(base + r)*64 + (c - 64)] = v;
    }
    __syncthreads();
    if (t < 64) {
        float s = 0.f;
        #pragma unroll 4
        for (int c = 0; c < 60; c++) { float v = outp[t*132 + c]; s += v*v; }
        g_ikn[base + t] = rsqrtf(s);
    }
}

// ---------------------------------------------------------------------------
// Kernel 2: fused attention. 128 q/block, 2 CTAs/SM.
// NEW Q-proj warp map: warp = (n-tile w&3, m-pair w>>2); Wq redundancy 4x->2x.
// ---------------------------------------------------------------------------
#define AS_Q   0            // 128 x 68 = 8704  (dead after kt loop -> Rp stage)
#define BUF_K  8704         // 64 x 68
#define BUF_V  13056        // 64 x 68
#define S_KN   17408        // 64
#define S_PB   17472        // 64
#define AS_P   17536        // 128 x 68 -> ends 26240
#define AS_O   8704         // overlay on BUF region after kt loop (128 x 68)
#define AS_RW  0            // Rp chunk stage: 64 x 68 (overlays dead AS_Q)
#define AS_QN  26240        // 128
#define AS_L   26368        // 128
#define AS_IT  26496        // 128 ints
#define ATT_FLOATS 26624    // 106,496 B -> 2 CTAs/SM
#define ATT_SMEM_BYTES (ATT_FLOATS*4)

__global__ __launch_bounds__(256, 2) void att_w(
    const int* __restrict__ titems, const float* __restrict__ tvec,
    const float* __restrict__ pos_bias, const float* __restrict__ Rb,
    float* __restrict__ out)
{
    extern __shared__ float sm[];
    const int t = threadIdx.x, lane = t & 31, w = t >> 5;
    const int b  = blockIdx.x >> 2;
    const int qt = blockIdx.x & 3;
    const int tok0 = b*NTQ + qt*128;

    int* it_s = (int*)(sm + AS_IT);
    if (t < 128) it_s[t] = titems[tok0 + t];
    __syncthreads();

    // ---- Q projection in two 64-row halves (gather staged over BUF..P) ----
    float* qemb = sm + BUF_K;   // 64 x 260 = 16640 fl, fits in [8704, 26240)
    for (int h = 0; h < 2; h++) {
        for (int r = w*8; r < w*8 + 8; r++) {
            const float4* src = (const float4*)(tvec + (size_t)it_s[h*64 + r]*EMB);
            float4* dst = (float4*)(qemb + r*260);
            #pragma unroll
            for (int i = lane; i < 64; i += 32) {
                float4 v = src[i];
                v.x = r32(v.x); v.y = r32(v.y); v.z = r32(v.z); v.w = r32(v.w);
                dst[i] = v;
            }
        }
        __syncthreads();
        {
            const int tn = w & 3;            // n-tile 0..3
            const int m0 = (w >> 2) * 2;     // m-tiles m0, m0+1
            CFrag acc[2];
            wmma::fill_fragment(acc[0], 0.f);
            wmma::fill_fragment(acc[1], 0.f);
            for (int k0 = 0; k0 < 256; k0 += 8) {
                BFragC bf;
                wmma::load_matrix_sync(bf, g_Wq + (size_t)tn*16*256 + k0, 256);
                #pragma unroll
                for (int m = 0; m < 2; m++) {
                    AFrag af;
                    wmma::load_matrix_sync(af, qemb + (m0+m)*16*260 + k0, 260);
                    wmma::mma_sync(acc[m], af, bf, acc[m]);
                }
            }
            #pragma unroll
            for (int m = 0; m < 2; m++)
                wmma::store_matrix_sync(sm + AS_Q + (h*64 + (m0+m)*16)*68 + tn*16,
                                        acc[m], 68, wmma::mem_row_major);
        }
        __syncthreads();
    }
    // bias + pre-round Q; inverse query norms; L init
    for (int idx = t; idx < 8192; idx += 256) {
        const int r = idx >> 6, c = idx & 63;
        sm[AS_Q + r*68 + c] = r32(sm[AS_Q + r*68 + c] + g_bq[c]);
    }
    __syncthreads();
    if (t < 128) {
        float s = 0.f;
        #pragma unroll 4
        for (int c = 0; c < 64; c++) { float v = sm[AS_Q + t*68 + c]; s += v*v; }
        sm[AS_QN + t] = rsqrtf(s);
        sm[AS_L + t] = 0.f;
    }
    __syncthreads();

    // ---- Q fragments register-resident (rows 16w..16w+15, pre-rounded) ----
    AFrag qf[8];
    #pragma unroll
    for (int k0 = 0; k0 < 8; k0++)
        wmma::load_matrix_sync(qf[k0], sm + AS_Q + w*16*68 + k0*8, 68);

    CFrag oacc[4];
    #pragma unroll
    for (int j = 0; j < 4; j++) wmma::fill_fragment(oacc[j], 0.f);

    for (int kt = 0; kt < 8; kt++) {
        // ---- load K/V tile (synchronous, float4) ----
        {
            const size_t gb = (size_t)(b*NCK + kt*64) * 64;
            const float4* Ksrc = (const float4*)(g_K + gb);
            const float4* Vsrc = (const float4*)(g_V + gb);
            #pragma unroll
            for (int i = 0; i < 4; i++) {
                const int idx = t + i*256;          // 0..1023
                const int r = idx >> 4, c = (idx & 15) * 4;
                *(float4*)(sm + BUF_K + r*68 + c) = Ksrc[idx];
                *(float4*)(sm + BUF_V + r*68 + c) = Vsrc[idx];
            }
            if (t < 64) {
                sm[S_KN + t] = g_ikn[b*NCK + kt*64 + t];
                sm[S_PB + t] = pos_bias[kt*64 + t];
            }
        }
        __syncthreads();

        // ---- scores: warp w computes P rows 16w..16w+15 ----
        {
            CFrag acc[4];
            #pragma unroll
            for (int j = 0; j < 4; j++) wmma::fill_fragment(acc[j], 0.f);
            #pragma unroll
            for (int k0 = 0; k0 < 8; k0++) {
                #pragma unroll
                for (int j = 0; j < 4; j++) {
                    BFragC bf;
                    wmma::load_matrix_sync(bf, sm + BUF_K + j*16*68 + k0*8, 68);
                    wmma::mma_sync(acc[j], qf[k0], bf, acc[j]);
                }
            }
            #pragma unroll
            for (int j = 0; j < 4; j++)
                wmma::store_matrix_sync(sm + AS_P + w*16*68 + j*16, acc[j], 68,
                                        wmma::mem_row_major);
        }
        __syncwarp();

        // ---- exp (warp-owned rows), store tf32-rounded P, accumulate L ----
        {
            const int q = w*16 + (lane >> 1);
            const int ha = lane & 1;
            const float iq = sm[AS_QN + q];
            float* Prow = sm + AS_P + q*68;
            float s = 0.f;
            #pragma unroll
            for (int j = 0; j < 32; j++) {
                const int k = ha*32 + j;
                const float p = r32(__expf(Prow[k] * (iq * sm[S_KN + k]) + sm[S_PB + k]));
                Prow[k] = p;
                s += p;
            }
            s += __shfl_xor_sync(0xffffffff, s, 1);
            if (ha == 0) sm[AS_L + q] += s;
        }
        __syncwarp();

        // ---- PV accumulate (A = own P rows, pre-rounded) ----
        #pragma unroll
        for (int k0 = 0; k0 < 8; k0++) {
            AFrag af;
            wmma::load_matrix_sync(af, sm + AS_P + w*16*68 + k0*8, 68);
            #pragma unroll
            for (int j = 0; j < 4; j++) {
                BFragR bf;
                wmma::load_matrix_sync(bf, sm + BUF_V + k0*8*68 + j*16, 68);
                wmma::mma_sync(oacc[j], af, bf, oacc[j]);
            }
        }
        __syncthreads();    // PV done before next tile overwrites K/V
    }

    // ---- finalize: O = oacc / L, pre-round (O overlays BUF region) ----
    #pragma unroll
    for (int j = 0; j < 4; j++)
        wmma::store_matrix_sync(sm + AS_O + w*16*68 + j*16, oacc[j], 68,
                                wmma::mem_row_major);
    __syncthreads();
    if (t < 128) sm[AS_QN + t] = 1.f / sm[AS_L + t];
    __syncthreads();
    for (int idx = t; idx < 8192; idx += 256) {
        const int r = idx >> 6, c = idx & 63;
        sm[AS_O + r*68 + c] = r32(sm[AS_O + r*68 + c] * sm[AS_QN + r]);
    }
    __syncthreads();

    // ---- output projection: O(128x64) @ Rp^T in 4 chunks of 64 cols.
    //      Rp chunk (64x64) staged through dead AS_Q region (ld 68). ----
    AFrag of[8];
    #pragma unroll
    for (int k0 = 0; k0 < 8; k0++)
        wmma::load_matrix_sync(of[k0], sm + AS_O + w*16*68 + k0*8, 68);
    for (int chunk = 0; chunk < 4; chunk++) {
        // stage g_Rp rows [chunk*64, +64), 64 cols -> AS_RW [64][68]
        {
            const float4* Rsrc = (const float4*)(g_Rp + (size_t)chunk*64*64);
            #pragma unroll
            for (int i = 0; i < 4; i++) {
                const int idx = t + i*256;          // 0..1023 float4
                const int r = idx >> 4, c = (idx & 15) * 4;
                *(float4*)(sm + AS_RW + r*68 + c) = Rsrc[idx];
            }
        }
        __syncthreads();

        CFrag acc[4];
        #pragma unroll
        for (int j = 0; j < 4; j++) wmma::fill_fragment(acc[j], 0.f);
        #pragma unroll
        for (int k0 = 0; k0 < 8; k0++) {
            #pragma unroll
            for (int j = 0; j < 4; j++) {
                BFragC bf;
                wmma::load_matrix_sync(bf, sm + AS_RW + j*16*68 + k0*8, 68);
                wmma::mma_sync(acc[j], of[k0], bf, acc[j]);
            }
        }
        #pragma unroll
        for (int j = 0; j < 4; j++)
            wmma::store_matrix_sync(sm + AS_P + w*16*68 + j*16, acc[j], 68,
                                    wmma::mem_row_major);
        __syncthreads();
        const int e0 = chunk*64;
        for (int idx = t; idx < 8192; idx += 256) {
            const int r = idx >> 6, c = idx & 63;
            out[(size_t)(tok0 + r)*EMB + e0 + c] = sm[AS_P + r*68 + c] + Rb[e0 + c];
        }
        __syncthreads();
    }
}

// ---------------------------------------------------------------------------
extern "C" void kernel_launch(void* const* d_in, const int* in_sizes, int n_in,
                              void* d_out, int out_size)
{
    (void)in_sizes; (void)n_in; (void)out_size;
    const int*   titems = (const int*)  d_in[0];
    const int*   citems = (const int*)  d_in[1];
    const float* tvec   = (const float*)d_in[2];
    const float* cvec   = (const float*)d_in[3];
    const float* Atw    = (const float*)d_in[4];
    const float* Atb    = (const float*)d_in[5];
    const float* Acw    = (const float*)d_in[6];
    const float* Acb    = (const float*)d_in[7];
    const float* Bcw    = (const float*)d_in[8];
    const float* Bcb    = (const float*)d_in[9];
    const float* pb     = (const float*)d_in[10];
    const float* Rw     = (const float*)d_in[11];
    const float* Rb     = (const float*)d_in[12];
    float* out = (float*)d_out;

    prep_kernel<<<128, 256>>>(Atw, Atb, Acw, Acb, Bcw, Bcb, Rw);

    cudaFuncSetAttribute(kv_proj_w, cudaFuncAttributeMaxDynamicSharedMemorySize,
                         KV_SMEM_BYTES);
    kv_proj_w<<<NTOK/64, 256, KV_SMEM_BYTES>>>(citems, cvec);

    cudaFuncSetAttribute(att_w, cudaFuncAttributeMaxDynamicSharedMemorySize,
                         ATT_SMEM_BYTES);
    att_w<<<BATCH*(NTQ/128), 256, ATT_SMEM_BYTES>>>(titems, tvec, pb, Rb, out);
}

// round 17
// speedup vs baseline: 1.3706x; 1.0048x over previous
#include <cuda_runtime.h>
#include <mma.h>
#include <math.h>
#include <cstdint>

using namespace nvcuda;

#define BATCH 128
#define NTQ   512
#define NCK   512
#define EMB   256
#define NTOK  (BATCH*NCK)

// ---- device scratch (allocation-free) ----
__device__ float g_K[NTOK*64];      // K padded, tf32-pre-rounded
__device__ float g_V[NTOK*64];      // V padded, tf32-pre-rounded
__device__ float g_ikn[NTOK];       // inverse key norms
__device__ float g_Wq[64*256];      // At_w padded, tf32-pre-rounded
__device__ float g_Wc[128*256];     // [Ac_w; pad; Bc_w; pad], tf32-pre-rounded
__device__ float g_Rp[256*64];      // R_w padded, tf32-pre-rounded
__device__ float g_bq[64];
__device__ float g_bc[128];

__device__ __forceinline__ float r32(float x) { return wmma::__float_to_tf32(x); }

typedef wmma::fragment<wmma::matrix_a, 16,16,8, wmma::precision::tf32, wmma::row_major> AFrag;
typedef wmma::fragment<wmma::matrix_b, 16,16,8, wmma::precision::tf32, wmma::col_major> BFragC;
typedef wmma::fragment<wmma::matrix_b, 16,16,8, wmma::precision::tf32, wmma::row_major> BFragR;
typedef wmma::fragment<wmma::accumulator, 16,16,8, float> CFrag;

__device__ __forceinline__ void cp16(uint32_t dst, const void* src) {
    asm volatile("cp.async.cg.shared.global [%0], [%1], 16;" :: "r"(dst), "l"(src));
}

// ---------------------------------------------------------------------------
__global__ void prep_kernel(const float* __restrict__ Atw, const float* __restrict__ Atb,
                            const float* __restrict__ Acw, const float* __restrict__ Acb,
                            const float* __restrict__ Bcw, const float* __restrict__ Bcb,
                            const float* __restrict__ Rw)
{
    const int i = blockIdx.x*blockDim.x + threadIdx.x;
    const int stride = gridDim.x*blockDim.x;
    for (int idx = i; idx < 64*256; idx += stride) {
        int d = idx >> 8, e = idx & 255;
        g_Wq[idx] = (d < 60) ? r32(Atw[d*256+e]) : 0.f;
    }
    for (int idx = i; idx < 128*256; idx += stride) {
        int d = idx >> 8, e = idx & 255;
        float v = 0.f;
        if (d < 60) v = r32(Acw[d*256+e]);
        else if (d >= 64 && d < 124) v = r32(Bcw[(d-64)*256+e]);
        g_Wc[idx] = v;
    }
    for (int idx = i; idx < 256*64; idx += stride) {
        int e = idx >> 6, dv = idx & 63;
        g_Rp[idx] = (dv < 60) ? r32(Rw[e*60+dv]) : 0.f;
    }
    if (i < 64)  g_bq[i] = (i < 60) ? Atb[i] : 0.f;
    if (i < 128) g_bc[i] = (i < 60) ? Acb[i] : ((i >= 64 && i < 124) ? Bcb[i-64] : 0.f);
}

// ---------------------------------------------------------------------------
// Kernel 1: K/V projection. 64 tokens/block, 2 CTAs/SM, 1024 blocks.
// Warp w owns n-tile w (1x B redundancy), iterates all 4 m-tiles.
// ---------------------------------------------------------------------------
#define KV_CEMB 0                    // 64 x 260 = 16640
#define KV_OUT  16640                // 64 x 132 = 8448
#define KV_IT   (16640+8448)         // 64 ints
#define KV_FLOATS (16640+8448+64)    // 25152 fl = 100.6 KB -> 2 CTAs/SM
#define KV_SMEM_BYTES (KV_FLOATS*4)

__global__ __launch_bounds__(256, 2) void kv_proj_w(
    const int* __restrict__ citems, const float* __restrict__ cvec)
{
    extern __shared__ float sm[];
    float* cemb = sm + KV_CEMB;
    float* outp = sm + KV_OUT;
    int*   items = (int*)(sm + KV_IT);

    const int t = threadIdx.x, lane = t & 31, w = t >> 5;
    const int base = blockIdx.x * 64;

    if (t < 64) items[t] = citems[base + t];
    __syncthreads();

    for (int r = w*8; r < w*8 + 8; r++) {
        const float4* src = (const float4*)(cvec + (size_t)items[r]*EMB);
        float4* dst = (float4*)(cemb + r*260);
        #pragma unroll
        for (int i = lane; i < 64; i += 32) {
            float4 v = src[i];
            v.x = r32(v.x); v.y = r32(v.y); v.z = r32(v.z); v.w = r32(v.w);
            dst[i] = v;
        }
    }
    __syncthreads();

    {
        const int nt = w;                // n-tile 0..7 (one per warp)
        CFrag acc[4];
        #pragma unroll
        for (int m = 0; m < 4; m++) wmma::fill_fragment(acc[m], 0.f);
        for (int k0 = 0; k0 < 256; k0 += 8) {
            BFragC bf;
            wmma::load_matrix_sync(bf, g_Wc + (size_t)nt*16*256 + k0, 256);
            #pragma unroll
            for (int m = 0; m < 4; m++) {
                AFrag af;
                wmma::load_matrix_sync(af, cemb + m*16*260 + k0, 260);
                wmma::mma_sync(acc[m], af, bf, acc[m]);
            }
        }
        #pragma unroll
        for (int m = 0; m < 4; m++)
            wmma::store_matrix_sync(outp + m*16*132 + nt*16, acc[m], 132,
                                    wmma::mem_row_major);
    }
    __syncthreads();

    for (int idx = t; idx < 8192; idx += 256) {
        const int r = idx >> 7, c = idx & 127;
        float v = r32(outp[r*132 + c] + g_bc[c]);
        outp[r*132 + c] = v;
        if (c < 64) g_K[(size_t)(base + r)*64 + c]        = v;
        else        g_V[(size_t)(base + r)*64 + (c - 64)] = v;
    }
    __syncthreads();
    if (t < 64) {
        float s = 0.f;
        #pragma unroll 4
        for (int c = 0; c < 60; c++) { float v = outp[t*132 + c]; s += v*v; }
        g_ikn[base + t] = rsqrtf(s);
    }
}

// ---------------------------------------------------------------------------
// Kernel 2: fused attention. 128 q/block, 2 CTAs/SM.
// K/V double-buffered via cp.async, buffer 1 = dead AS_Q region.
// One __syncthreads per tile.
// ---------------------------------------------------------------------------
#define AS_Q   0            // 128 x 68 = 8704; becomes K/V buffer 1 in kt loop
#define BUF0   8704         // K/V buffer 0: K at +0 (64x68), V at +4352
#define AS_P   17536        // 128 x 68 -> ends 26240
#define AS_O   8704         // overlay on BUF0 region after kt loop (128 x 68)
#define AS_RW  0            // Rp chunk stage: 64 x 68 (overlays buffer 1)
#define AS_QN  26240        // 128
#define AS_L   26368        // 128
#define AS_IT  26496        // 128 ints
#define S_KNB  26624        // 2 x {KN 64, PB 64} = 256
#define ATT_FLOATS 26880    // 107,520 B -> 2 CTAs/SM
#define ATT_SMEM_BYTES (ATT_FLOATS*4)

__global__ __launch_bounds__(256, 2) void att_w(
    const int* __restrict__ titems, const float* __restrict__ tvec,
    const float* __restrict__ pos_bias, const float* __restrict__ Rb,
    float* __restrict__ out)
{
    extern __shared__ float sm[];
    const int t = threadIdx.x, lane = t & 31, w = t >> 5;
    const int b  = blockIdx.x >> 2;
    const int qt = blockIdx.x & 3;
    const int tok0 = b*NTQ + qt*128;
    const uint32_t smb = (uint32_t)__cvta_generic_to_shared(sm);

    int* it_s = (int*)(sm + AS_IT);
    if (t < 128) it_s[t] = titems[tok0 + t];
    __syncthreads();

    // ---- Q projection in two 64-row halves (gather staged over BUF0..P) ----
    float* qemb = sm + BUF0;   // 64 x 260 = 16640 fl, fits in [8704, 26240)
    for (int h = 0; h < 2; h++) {
        for (int r = w*8; r < w*8 + 8; r++) {
            const float4* src = (const float4*)(tvec + (size_t)it_s[h*64 + r]*EMB);
            float4* dst = (float4*)(qemb + r*260);
            #pragma unroll
            for (int i = lane; i < 64; i += 32) {
                float4 v = src[i];
                v.x = r32(v.x); v.y = r32(v.y); v.z = r32(v.z); v.w = r32(v.w);
                dst[i] = v;
            }
        }
        __syncthreads();
        {
            const int tn = w & 3;            // n-tile 0..3
            const int m0 = (w >> 2) * 2;     // m-tiles m0, m0+1
            CFrag acc[2];
            wmma::fill_fragment(acc[0], 0.f);
            wmma::fill_fragment(acc[1], 0.f);
            for (int k0 = 0; k0 < 256; k0 += 8) {
                BFragC bf;
                wmma::load_matrix_sync(bf, g_Wq + (size_t)tn*16*256 + k0, 256);
                #pragma unroll
                for (int m = 0; m < 2; m++) {
                    AFrag af;
                    wmma::load_matrix_sync(af, qemb + (m0+m)*16*260 + k0, 260);
                    wmma::mma_sync(acc[m], af, bf, acc[m]);
                }
            }
            #pragma unroll
            for (int m = 0; m < 2; m++)
                wmma::store_matrix_sync(sm + AS_Q + (h*64 + (m0+m)*16)*68 + tn*16,
                                        acc[m], 68, wmma::mem_row_major);
        }
        __syncthreads();
    }
    // bias + pre-round Q; inverse query norms; L init
    for (int idx = t; idx < 8192; idx += 256) {
        const int r = idx >> 6, c = idx & 63;
        sm[AS_Q + r*68 + c] = r32(sm[AS_Q + r*68 + c] + g_bq[c]);
    }
    __syncthreads();
    if (t < 128) {
        float s = 0.f;
        #pragma unroll 4
        for (int c = 0; c < 64; c++) { float v = sm[AS_Q + t*68 + c]; s += v*v; }
        sm[AS_QN + t] = rsqrtf(s);
        sm[AS_L + t] = 0.f;
    }
    __syncthreads();

    // ---- Q fragments register-resident (rows 16w..16w+15, pre-rounded) ----
    AFrag qf[8];
    #pragma unroll
    for (int k0 = 0; k0 < 8; k0++)
        wmma::load_matrix_sync(qf[k0], sm + AS_Q + w*16*68 + k0*8, 68);
    // NOTE: AS_Q is dead from here until after the kt loop -> K/V buffer 1.

    // buffer bases (floats): tile kt uses buffer kt&1
    const int bufK[2] = {BUF0, 0};

    // prefetch helper: tile kt2 into buffer bi
    auto prefetch = [&](int bi, int kt2) {
        const size_t gb = (size_t)(b*NCK + kt2*64) * 64;
        const float* Kg = g_K + gb;
        const float* Vg = g_V + gb;
        const int kb = bufK[bi];
        #pragma unroll
        for (int i = 0; i < 4; i++) {
            const int idx = t + i*256;          // 0..1023 float4 slots
            const int r = idx >> 4, c = (idx & 15) * 4;
            cp16(smb + (uint32_t)(kb +        r*68 + c)*4, Kg + r*64 + c);
            cp16(smb + (uint32_t)(kb + 4352 + r*68 + c)*4, Vg + r*64 + c);
        }
        if (t < 16)      cp16(smb + (uint32_t)(S_KNB + bi*128 + t*4)*4,
                              g_ikn + b*NCK + kt2*64 + t*4);
        else if (t < 32) cp16(smb + (uint32_t)(S_KNB + bi*128 + 64 + (t-16)*4)*4,
                              pos_bias + kt2*64 + (t-16)*4);
        asm volatile("cp.async.commit_group;" ::: "memory");
    };

    __syncthreads();              // all warps have qf loaded; buffers free
    prefetch(0, 0);

    CFrag oacc[4];
    #pragma unroll
    for (int j = 0; j < 4; j++) wmma::fill_fragment(oacc[j], 0.f);

    for (int kt = 0; kt < 8; kt++) {
        const int bi = kt & 1;
        const int kb = bufK[bi];
        asm volatile("cp.async.wait_group 0;" ::: "memory");
        __syncthreads();          // tile kt arrived AND all warps done with kt-1

        if (kt < 7) prefetch(1 - bi, kt + 1);   // into buffer of tile kt-1

        // ---- scores: warp w computes P rows 16w..16w+15 ----
        {
            CFrag acc[4];
            #pragma unroll
            for (int j = 0; j < 4; j++) wmma::fill_fragment(acc[j], 0.f);
            #pragma unroll
            for (int k0 = 0; k0 < 8; k0++) {
                #pragma unroll
                for (int j = 0; j < 4; j++) {
                    BFragC bf;
                    wmma::load_matrix_sync(bf, sm + kb + j*16*68 + k0*8, 68);
                    wmma::mma_sync(acc[j], qf[k0], bf, acc[j]);
                }
            }
            #pragma unroll
            for (int j = 0; j < 4; j++)
                wmma::store_matrix_sync(sm + AS_P + w*16*68 + j*16, acc[j], 68,
                                        wmma::mem_row_major);
        }
        __syncwarp();

        // ---- exp (warp-owned rows), store tf32-rounded P, accumulate L ----
        {
            const int q = w*16 + (lane >> 1);
            const int ha = lane & 1;
            const float iq = sm[AS_QN + q];
            float* Prow = sm + AS_P + q*68;
            const float* knp = sm + S_KNB + bi*128;
            const float* pbp = knp + 64;
            float s = 0.f;
            #pragma unroll
            for (int j = 0; j < 32; j++) {
                const int k = ha*32 + j;
                const float p = r32(__expf(Prow[k] * (iq * knp[k]) + pbp[k]));
                Prow[k] = p;
                s += p;
            }
            s += __shfl_xor_sync(0xffffffff, s, 1);
            if (ha == 0) sm[AS_L + q] += s;
        }
        __syncwarp();

        // ---- PV accumulate (A = own P rows, pre-rounded) ----
        #pragma unroll
        for (int k0 = 0; k0 < 8; k0++) {
            AFrag af;
            wmma::load_matrix_sync(af, sm + AS_P + w*16*68 + k0*8, 68);
            #pragma unroll
            for (int j = 0; j < 4; j++) {
                BFragR bf;
                wmma::load_matrix_sync(bf, sm + kb + 4352 + k0*8*68 + j*16, 68);
                wmma::mma_sync(oacc[j], af, bf, oacc[j]);
            }
        }
        // no bottom barrier: next iteration's top barrier covers buffer reuse
    }
    __syncthreads();    // all warps done with buffers before O overlays them

    // ---- finalize: O = oacc / L, pre-round (O overlays BUF0 region) ----
    #pragma unroll
    for (int j = 0; j < 4; j++)
        wmma::store_matrix_sync(sm + AS_O + w*16*68 + j*16, oacc[j], 68,
                                wmma::mem_row_major);
    __syncthreads();
    if (t < 128) sm[AS_QN + t] = 1.f / sm[AS_L + t];
    __syncthreads();
    for (int idx = t; idx < 8192; idx += 256) {
        const int r = idx >> 6, c = idx & 63;
        sm[AS_O + r*68 + c] = r32(sm[AS_O + r*68 + c] * sm[AS_QN + r]);
    }
    __syncthreads();

    // ---- output projection: O(128x64) @ Rp^T in 4 chunks of 64 cols.
    //      Rp chunk (64x64) staged through dead buffer-1 region (ld 68). ----
    AFrag of[8];
    #pragma unroll
    for (int k0 = 0; k0 < 8; k0++)
        wmma::load_matrix_sync(of[k0], sm + AS_O + w*16*68 + k0*8, 68);
    for (int chunk = 0; chunk < 4; chunk++) {
        {
            const float4* Rsrc = (const float4*)(g_Rp + (size_t)chunk*64*64);
            #pragma unroll
            for (int i = 0; i < 4; i++) {
                const int idx = t + i*256;          // 0..1023 float4
                const int r = idx >> 4, c = (idx & 15) * 4;
                *(float4*)(sm + AS_RW + r*68 + c) = Rsrc[idx];
            }
        }
        __syncthreads();

        CFrag acc[4];
        #pragma unroll
        for (int j = 0; j < 4; j++) wmma::fill_fragment(acc[j], 0.f);
        #pragma unroll
        for (int k0 = 0; k0 < 8; k0++) {
            #pragma unroll
            for (int j = 0; j < 4; j++) {
                BFragC bf;
                wmma::load_matrix_sync(bf, sm + AS_RW + j*16*68 + k0*8, 68);
                wmma::mma_sync(acc[j], of[k0], bf, acc[j]);
            }
        }
        #pragma unroll
        for (int j = 0; j < 4; j++)
            wmma::store_matrix_sync(sm + AS_P + w*16*68 + j*16, acc[j], 68,
                                    wmma::mem_row_major);
        __syncthreads();
        const int e0 = chunk*64;
        for (int idx = t; idx < 8192; idx += 256) {
            const int r = idx >> 6, c = idx & 63;
            out[(size_t)(tok0 + r)*EMB + e0 + c] = sm[AS_P + r*68 + c] + Rb[e0 + c];
        }
        __syncthreads();
    }
}

// ---------------------------------------------------------------------------
extern "C" void kernel_launch(void* const* d_in, const int* in_sizes, int n_in,
                              void* d_out, int out_size)
{
    (void)in_sizes; (void)n_in; (void)out_size;
    const int*   titems = (const int*)  d_in[0];
    const int*   citems = (const int*)  d_in[1];
    const float* tvec   = (const float*)d_in[2];
    const float* cvec   = (const float*)d_in[3];
    const float* Atw    = (const float*)d_in[4];
    const float* Atb    = (const float*)d_in[5];
    const float* Acw    = (const float*)d_in[6];
    const float* Acb    = (const float*)d_in[7];
    const float* Bcw    = (const float*)d_in[8];
    const float* Bcb    = (const float*)d_in[9];
    const float* pb     = (const float*)d_in[10];
    const float* Rw     = (const float*)d_in[11];
    const float* Rb     = (const float*)d_in[12];
    float* out = (float*)d_out;

    prep_kernel<<<128, 256>>>(Atw, Atb, Acw, Acb, Bcw, Bcb, Rw);

    cudaFuncSetAttribute(kv_proj_w, cudaFuncAttributeMaxDynamicSharedMemorySize,
                         KV_SMEM_BYTES);
    kv_proj_w<<<NTOK/64, 256, KV_SMEM_BYTES>>>(citems, cvec);

    cudaFuncSetAttribute(att_w, cudaFuncAttributeMaxDynamicSharedMemorySize,
                         ATT_SMEM_BYTES);
    att_w<<<BATCH*(NTQ/128), 256, ATT_SMEM_BYTES>>>(titems, tvec, pb, Rb, out);
}